// round 13
// baseline (speedup 1.0000x reference)
#include <cuda_runtime.h>
#include <math.h>

constexpr int C  = 128;
constexpr int S  = 24;
constexpr int NV = S * S * S;      // 13824
constexpr int KW = 3;
constexpr int NW = KW * KW * KW;   // 27

__device__ float g_q[NV * C];
__device__ float g_k[NV * C];
__device__ float g_v[NV * C];
__device__ float g_bias[NW];
__device__ float g_wt[3 * C * C];  // transposed weights: [mat][c][o]

// ---------------------------------------------------------------------------
// Prep: bias table. 288 threads, one warp per partial sum.
// ---------------------------------------------------------------------------
__global__ void prep_kernel(const float* __restrict__ rh,
                            const float* __restrict__ rw,
                            const float* __restrict__ rd) {
    __shared__ float a[9];
    int w = threadIdx.x >> 5, lane = threadIdx.x & 31;
    if (w < 9) {
        const float* p = (w < 3) ? rh : (w < 6 ? rw : rd);
        int k = w % 3;
        float s = 0.f;
        for (int c = lane; c < 64; c += 32) s += p[c * 3 + k];
#pragma unroll
        for (int o = 16; o; o >>= 1) s += __shfl_xor_sync(0xffffffffu, s, o);
        if (lane == 0) a[w] = s;
    }
    __syncthreads();
    int t = threadIdx.x;
    if (t < NW)
        g_bias[t] = a[t / 9] + a[3 + (t / 3) % 3] + a[6 + t % 3];
}

// ---------------------------------------------------------------------------
// Weight transpose: g_wt[mat][c][o] = w[mat][o][c].  grid (4,4,3), block (32,8)
// ---------------------------------------------------------------------------
__global__ void wt_kernel(const float* __restrict__ w0,
                          const float* __restrict__ w1,
                          const float* __restrict__ w2) {
    __shared__ float t[32][33];
    int mat = blockIdx.z;
    const float* w = (mat == 0) ? w0 : (mat == 1 ? w1 : w2);
    int o0 = blockIdx.y * 32, c0 = blockIdx.x * 32;
    int tx = threadIdx.x;
    for (int i = threadIdx.y; i < 32; i += 8)
        t[i][tx] = w[(o0 + i) * C + c0 + tx];
    __syncthreads();
    float* dst = g_wt + mat * C * C;
    for (int i = threadIdx.y; i < 32; i += 8)
        dst[(c0 + i) * C + o0 + tx] = t[tx][i];
}

// ---------------------------------------------------------------------------
// GEMM: out[v][o] = sum_c wt[c][o] * x[c][v] + b[o]
// Block tile: 128 voxels x 128 channels. 256 threads, 8x8 register tile.
// K chunks of 16, register prefetch.
// ---------------------------------------------------------------------------
__global__ void __launch_bounds__(256, 2)
gemm_kernel(const float* __restrict__ x,
            const float* __restrict__ b0,
            const float* __restrict__ b1,
            const float* __restrict__ b2) {
    __shared__ float xs[16][128];
    __shared__ float ws[16][128];

    int mat = blockIdx.y;
    const float* wt   = g_wt + mat * C * C;
    const float* bias = (mat == 0) ? b0 : (mat == 1 ? b1 : b2);
    float* out = (mat == 0) ? g_q : (mat == 1 ? g_k : g_v);

    int tid = threadIdx.x;
    int tx = tid & 15, ty = tid >> 4;
    int v0 = blockIdx.x * 128;
    int ob = tx * 8;   // output-channel base for this thread
    int vb = ty * 8;   // voxel base for this thread

    // loader mapping: thread loads row lc, 8 floats at column lv
    int lc = tid >> 4;
    int lv = (tid & 15) * 8;

    float acc[8][8];
#pragma unroll
    for (int i = 0; i < 8; i++)
#pragma unroll
        for (int j = 0; j < 8; j++) acc[i][j] = 0.f;

    float4 px0, px1, pw0, pw1;
    {
        const float* xp = x + lc * NV + v0 + lv;
        px0 = *(const float4*)xp;
        px1 = *(const float4*)(xp + 4);
        const float* wp = wt + lc * C + lv;
        pw0 = *(const float4*)wp;
        pw1 = *(const float4*)(wp + 4);
    }

    for (int ch = 0; ch < 8; ch++) {
        __syncthreads();
        *(float4*)&xs[lc][lv]     = px0;
        *(float4*)&xs[lc][lv + 4] = px1;
        *(float4*)&ws[lc][lv]     = pw0;
        *(float4*)&ws[lc][lv + 4] = pw1;
        __syncthreads();

        if (ch < 7) {
            int c0 = (ch + 1) * 16;
            const float* xp = x + (c0 + lc) * NV + v0 + lv;
            px0 = *(const float4*)xp;
            px1 = *(const float4*)(xp + 4);
            const float* wp = wt + (c0 + lc) * C + lv;
            pw0 = *(const float4*)wp;
            pw1 = *(const float4*)(wp + 4);
        }

#pragma unroll 4
        for (int k = 0; k < 16; k++) {
            float4 xv0 = *(const float4*)&xs[k][vb];
            float4 xv1 = *(const float4*)&xs[k][vb + 4];
            float4 wv0 = *(const float4*)&ws[k][ob];
            float4 wv1 = *(const float4*)&ws[k][ob + 4];
            float xr[8] = {xv0.x, xv0.y, xv0.z, xv0.w, xv1.x, xv1.y, xv1.z, xv1.w};
            float wr[8] = {wv0.x, wv0.y, wv0.z, wv0.w, wv1.x, wv1.y, wv1.z, wv1.w};
#pragma unroll
            for (int i = 0; i < 8; i++)
#pragma unroll
                for (int j = 0; j < 8; j++)
                    acc[i][j] = fmaf(xr[i], wr[j], acc[i][j]);
        }
    }

    float4 bb0 = *(const float4*)(bias + ob);
    float4 bb1 = *(const float4*)(bias + ob + 4);
#pragma unroll
    for (int i = 0; i < 8; i++) {
        float* orow = out + (v0 + vb + i) * C + ob;
        float4 s0, s1;
        s0.x = acc[i][0] + bb0.x; s0.y = acc[i][1] + bb0.y;
        s0.z = acc[i][2] + bb0.z; s0.w = acc[i][3] + bb0.w;
        s1.x = acc[i][4] + bb1.x; s1.y = acc[i][5] + bb1.y;
        s1.z = acc[i][6] + bb1.z; s1.w = acc[i][7] + bb1.w;
        *(float4*)orow       = s0;
        *(float4*)(orow + 4) = s1;
    }
}

// ---------------------------------------------------------------------------
// Attention: one block per voxel, 128 threads (thread = channel).
// ---------------------------------------------------------------------------
__global__ void attn_kernel(const float* __restrict__ bk,
                            const float* __restrict__ bv,
                            float* __restrict__ out) {
    __shared__ float qsh[C];
    __shared__ float logit[NW];
    __shared__ float probs[NW];
    __shared__ int   nidx[NW];
    __shared__ float wsum[4];

    int tid  = threadIdx.x;
    int lane = tid & 31;
    int wid  = tid >> 5;

    int v = blockIdx.x;
    int d = v % S;
    int w = (v / S) % S;
    int h = v / (S * S);

    float qc = g_q[v * C + tid];
    qsh[tid] = qc;

    if (tid < NW) {
        int i = tid / 9, j = (tid / 3) % 3, l = tid % 3;
        int hh = h + i - 1, ww = w + j - 1, dd = d + l - 1;
        bool ok = (unsigned)hh < (unsigned)S && (unsigned)ww < (unsigned)S &&
                  (unsigned)dd < (unsigned)S;
        nidx[tid] = ok ? ((hh * S + ww) * S + dd) : -1;
    }

    float r = qc;
#pragma unroll
    for (int o = 16; o; o >>= 1) r += __shfl_xor_sync(0xffffffffu, r, o);
    if (lane == 0) wsum[wid] = r;
    __syncthreads();

    const float4* q4 = (const float4*)qsh;
    float4 qv = q4[lane];
    for (int s = wid; s < NW; s += 4) {
        int n = nidx[s];
        const float* kp = (n >= 0) ? (g_k + n * C) : bk;
        float4 kv = ((const float4*)kp)[lane];
        float p = qv.x * kv.x + qv.y * kv.y + qv.z * kv.z + qv.w * kv.w;
#pragma unroll
        for (int o = 16; o; o >>= 1) p += __shfl_xor_sync(0xffffffffu, p, o);
        if (lane == 0) logit[s] = p;
    }
    __syncthreads();

    if (wid == 0) {
        float qs = wsum[0] + wsum[1] + wsum[2] + wsum[3];
        float li = (lane < NW) ? (logit[lane] + qs * g_bias[lane]) : -INFINITY;
        float m = li;
#pragma unroll
        for (int o = 16; o; o >>= 1) m = fmaxf(m, __shfl_xor_sync(0xffffffffu, m, o));
        float p = (lane < NW) ? __expf(li - m) : 0.f;
        float ssum = p;
#pragma unroll
        for (int o = 16; o; o >>= 1) ssum += __shfl_xor_sync(0xffffffffu, ssum, o);
        if (lane < NW) probs[lane] = p / ssum;
    }
    __syncthreads();

    float acc = 0.f;
#pragma unroll
    for (int s = 0; s < NW; s++) {
        int n = nidx[s];
        const float* vp = (n >= 0) ? (g_v + n * C) : bv;
        acc = fmaf(probs[s], vp[tid], acc);
    }
    out[v * C + tid] = acc;
}

// ---------------------------------------------------------------------------
// Launch.  Inputs: x, wq, bq, wk, bk, wv, bv, rel_h, rel_w, rel_d
// ---------------------------------------------------------------------------
extern "C" void kernel_launch(void* const* d_in, const int* in_sizes, int n_in,
                              void* d_out, int out_size) {
    const float* x   = (const float*)d_in[0];
    const float* wq  = (const float*)d_in[1];
    const float* bq  = (const float*)d_in[2];
    const float* wk  = (const float*)d_in[3];
    const float* bk  = (const float*)d_in[4];
    const float* wv  = (const float*)d_in[5];
    const float* bv  = (const float*)d_in[6];
    const float* rh  = (const float*)d_in[7];
    const float* rw  = (const float*)d_in[8];
    const float* rd  = (const float*)d_in[9];
    float* out = (float*)d_out;

    prep_kernel<<<1, 288>>>(rh, rw, rd);

    dim3 tgrid(4, 4, 3);
    wt_kernel<<<tgrid, dim3(32, 8)>>>(wq, wk, wv);

    dim3 ggrid(NV / 128, 3);
    gemm_kernel<<<ggrid, 256>>>(x, bq, bk, bv);

    attn_kernel<<<NV, 128>>>(bk, bv, out);
}

// round 14
// speedup vs baseline: 1.1951x; 1.1951x over previous
#include <cuda_runtime.h>
#include <math.h>

constexpr int C  = 128;
constexpr int S  = 24;
constexpr int NV = S * S * S;      // 13824
constexpr int KW = 3;
constexpr int NW = KW * KW * KW;   // 27

__device__ float g_q[NV * C];
__device__ float g_k[NV * C];
__device__ float g_v[NV * C];
__device__ float g_bias[NW];
__device__ float g_wt[3 * C * C];  // transposed weights: [mat][c][o]

typedef unsigned long long u64;

// ---- packed f32x2 helpers (Blackwell FFMA2 path, PTX-only) -----------------
__device__ __forceinline__ u64 pk2(float lo, float hi) {
    u64 d;
    asm("mov.b64 %0, {%1, %2};" : "=l"(d) : "f"(lo), "f"(hi));
    return d;
}
__device__ __forceinline__ void fma2(u64& c, u64 a, u64 b) {
    asm("fma.rn.f32x2 %0, %1, %2, %0;" : "+l"(c) : "l"(a), "l"(b));
}
__device__ __forceinline__ float2 up2(u64 d) {
    float2 r;
    asm("mov.b64 {%0, %1}, %2;" : "=f"(r.x), "=f"(r.y) : "l"(d));
    return r;
}

// ---------------------------------------------------------------------------
// Prep: bias table. 288 threads, one warp per partial sum.
// ---------------------------------------------------------------------------
__global__ void prep_kernel(const float* __restrict__ rh,
                            const float* __restrict__ rw,
                            const float* __restrict__ rd) {
    __shared__ float a[9];
    int w = threadIdx.x >> 5, lane = threadIdx.x & 31;
    if (w < 9) {
        const float* p = (w < 3) ? rh : (w < 6 ? rw : rd);
        int k = w % 3;
        float s = 0.f;
        for (int c = lane; c < 64; c += 32) s += p[c * 3 + k];
#pragma unroll
        for (int o = 16; o; o >>= 1) s += __shfl_xor_sync(0xffffffffu, s, o);
        if (lane == 0) a[w] = s;
    }
    __syncthreads();
    int t = threadIdx.x;
    if (t < NW)
        g_bias[t] = a[t / 9] + a[3 + (t / 3) % 3] + a[6 + t % 3];
}

// ---------------------------------------------------------------------------
// Weight transpose: g_wt[mat][c][o] = w[mat][o][c].  grid (4,4,3), block (32,8)
// ---------------------------------------------------------------------------
__global__ void wt_kernel(const float* __restrict__ w0,
                          const float* __restrict__ w1,
                          const float* __restrict__ w2) {
    __shared__ float t[32][33];
    int mat = blockIdx.z;
    const float* w = (mat == 0) ? w0 : (mat == 1 ? w1 : w2);
    int o0 = blockIdx.y * 32, c0 = blockIdx.x * 32;
    int tx = threadIdx.x;
    for (int i = threadIdx.y; i < 32; i += 8)
        t[i][tx] = w[(o0 + i) * C + c0 + tx];
    __syncthreads();
    float* dst = g_wt + mat * C * C;
    for (int i = threadIdx.y; i < 32; i += 8)
        dst[(c0 + i) * C + o0 + tx] = t[tx][i];
}

// ---------------------------------------------------------------------------
// GEMM: out[v][o] = sum_c wt[c][o] * x[c][v] + b[o]
// Block tile 128 voxels x 128 channels, 256 threads.
// Register tile 8 voxels x 8 channels, computed as 8 x 4 packed f32x2 pairs
// (channel pairs), using fma.rn.f32x2 for 2x fp32 FMA throughput.
// ---------------------------------------------------------------------------
__global__ void __launch_bounds__(256, 2)
gemm_kernel(const float* __restrict__ x,
            const float* __restrict__ b0,
            const float* __restrict__ b1,
            const float* __restrict__ b2) {
    __shared__ float xs[16][128];
    __shared__ float ws[16][128];

    int mat = blockIdx.y;
    const float* wt   = g_wt + mat * C * C;
    const float* bias = (mat == 0) ? b0 : (mat == 1 ? b1 : b2);
    float* out = (mat == 0) ? g_q : (mat == 1 ? g_k : g_v);

    int tid = threadIdx.x;
    int tx = tid & 15, ty = tid >> 4;
    int v0 = blockIdx.x * 128;
    int ob = tx * 8;   // output-channel base
    int vb = ty * 8;   // voxel base

    int lc = tid >> 4;
    int lv = (tid & 15) * 8;

    u64 acc[8][4];
#pragma unroll
    for (int i = 0; i < 8; i++)
#pragma unroll
        for (int j = 0; j < 4; j++) acc[i][j] = 0ull;  // two packed +0.0f

    float4 px0, px1, pw0, pw1;
    {
        const float* xp = x + lc * NV + v0 + lv;
        px0 = *(const float4*)xp;
        px1 = *(const float4*)(xp + 4);
        const float* wp = wt + lc * C + lv;
        pw0 = *(const float4*)wp;
        pw1 = *(const float4*)(wp + 4);
    }

    for (int ch = 0; ch < 8; ch++) {
        __syncthreads();
        *(float4*)&xs[lc][lv]     = px0;
        *(float4*)&xs[lc][lv + 4] = px1;
        *(float4*)&ws[lc][lv]     = pw0;
        *(float4*)&ws[lc][lv + 4] = pw1;
        __syncthreads();

        if (ch < 7) {
            int c0 = (ch + 1) * 16;
            const float* xp = x + (c0 + lc) * NV + v0 + lv;
            px0 = *(const float4*)xp;
            px1 = *(const float4*)(xp + 4);
            const float* wp = wt + (c0 + lc) * C + lv;
            pw0 = *(const float4*)wp;
            pw1 = *(const float4*)(wp + 4);
        }

#pragma unroll 4
        for (int k = 0; k < 16; k++) {
            float4 xv0 = *(const float4*)&xs[k][vb];
            float4 xv1 = *(const float4*)&xs[k][vb + 4];
            float4 wv0 = *(const float4*)&ws[k][ob];
            float4 wv1 = *(const float4*)&ws[k][ob + 4];
            u64 wp2[4];
            wp2[0] = pk2(wv0.x, wv0.y);
            wp2[1] = pk2(wv0.z, wv0.w);
            wp2[2] = pk2(wv1.x, wv1.y);
            wp2[3] = pk2(wv1.z, wv1.w);
            float xr[8] = {xv0.x, xv0.y, xv0.z, xv0.w,
                           xv1.x, xv1.y, xv1.z, xv1.w};
#pragma unroll
            for (int i = 0; i < 8; i++) {
                u64 xb = pk2(xr[i], xr[i]);
#pragma unroll
                for (int j = 0; j < 4; j++)
                    fma2(acc[i][j], xb, wp2[j]);
            }
        }
    }

    float4 bb0 = *(const float4*)(bias + ob);
    float4 bb1 = *(const float4*)(bias + ob + 4);
#pragma unroll
    for (int i = 0; i < 8; i++) {
        float2 a0 = up2(acc[i][0]);
        float2 a1 = up2(acc[i][1]);
        float2 a2 = up2(acc[i][2]);
        float2 a3 = up2(acc[i][3]);
        float* orow = out + (v0 + vb + i) * C + ob;
        float4 s0, s1;
        s0.x = a0.x + bb0.x; s0.y = a0.y + bb0.y;
        s0.z = a1.x + bb0.z; s0.w = a1.y + bb0.w;
        s1.x = a2.x + bb1.x; s1.y = a2.y + bb1.y;
        s1.z = a3.x + bb1.z; s1.w = a3.y + bb1.w;
        *(float4*)orow       = s0;
        *(float4*)(orow + 4) = s1;
    }
}

// ---------------------------------------------------------------------------
// Attention: one WARP per voxel. 256 threads = 8 warps = one 2x2x2 voxel cube
// per block (L1 locality for shared K/V neighbor rows). Softmax fully
// in-warp (27 <= 32 lanes): no __syncthreads, no smem staging.
// ---------------------------------------------------------------------------
__global__ void __launch_bounds__(256)
attn_kernel(const float* __restrict__ bk,
            const float* __restrict__ bv,
            float* __restrict__ out) {
    const unsigned FULL = 0xffffffffu;
    int lane = threadIdx.x & 31;
    int wrp  = threadIdx.x >> 5;

    // block -> 2x2x2 tile of voxels; warp -> voxel within tile
    int t = blockIdx.x;                 // 0 .. 12^3-1
    int tH = t / 144;
    int rr = t - tH * 144;
    int tW = rr / 12;
    int tD = rr - tW * 12;
    int h = tH * 2 + ((wrp >> 2) & 1);
    int w = tW * 2 + ((wrp >> 1) & 1);
    int d = tD * 2 + (wrp & 1);
    int v = (h * S + w) * S + d;

    // q: 4 channels per lane
    const float4 qv = *(const float4*)(g_q + v * C + lane * 4);

    // qsum over all 128 channels
    float qs = qv.x + qv.y + qv.z + qv.w;
#pragma unroll
    for (int o = 16; o; o >>= 1) qs += __shfl_xor_sync(FULL, qs, o);

    // neighbor index for lane s (< 27), else -1
    int ni = -1;
    float bias = 0.f;
    if (lane < NW) {
        int i = lane / 9, j = (lane / 3) % 3, l = lane % 3;
        int hh = h + i - 1, ww = w + j - 1, dd = d + l - 1;
        bool ok = (unsigned)hh < (unsigned)S && (unsigned)ww < (unsigned)S &&
                  (unsigned)dd < (unsigned)S;
        ni = ok ? ((hh * S + ww) * S + dd) : -1;
        bias = g_bias[lane];
    }

    // QK: 27 dot products; lane s keeps logit_s
    float logit = 0.f;
#pragma unroll
    for (int s = 0; s < NW; s++) {
        int ns = __shfl_sync(FULL, ni, s);
        const float* kp = (ns >= 0) ? (g_k + (size_t)ns * C) : bk;
        float4 kv = *(const float4*)(kp + lane * 4);
        float p = qv.x * kv.x;
        p = fmaf(qv.y, kv.y, p);
        p = fmaf(qv.z, kv.z, p);
        p = fmaf(qv.w, kv.w, p);
#pragma unroll
        for (int o = 16; o; o >>= 1) p += __shfl_xor_sync(FULL, p, o);
        if (lane == s) logit = p;
    }

    // softmax over 27, entirely in-warp
    float li = (lane < NW) ? fmaf(qs, bias, logit) : -INFINITY;
    float m = li;
#pragma unroll
    for (int o = 16; o; o >>= 1) m = fmaxf(m, __shfl_xor_sync(FULL, m, o));
    float p = (lane < NW) ? __expf(li - m) : 0.f;
    float ssum = p;
#pragma unroll
    for (int o = 16; o; o >>= 1) ssum += __shfl_xor_sync(FULL, ssum, o);
    float prob = p / ssum;

    // AV: weighted sum of 27 V rows, 4 channels per lane
    float4 acc = make_float4(0.f, 0.f, 0.f, 0.f);
#pragma unroll
    for (int s = 0; s < NW; s++) {
        int ns   = __shfl_sync(FULL, ni, s);
        float ps = __shfl_sync(FULL, prob, s);
        const float* vp = (ns >= 0) ? (g_v + (size_t)ns * C) : bv;
        float4 vv = *(const float4*)(vp + lane * 4);
        acc.x = fmaf(ps, vv.x, acc.x);
        acc.y = fmaf(ps, vv.y, acc.y);
        acc.z = fmaf(ps, vv.z, acc.z);
        acc.w = fmaf(ps, vv.w, acc.w);
    }
    *(float4*)(out + v * C + lane * 4) = acc;
}

// ---------------------------------------------------------------------------
// Launch.  Inputs: x, wq, bq, wk, bk, wv, bv, rel_h, rel_w, rel_d
// ---------------------------------------------------------------------------
extern "C" void kernel_launch(void* const* d_in, const int* in_sizes, int n_in,
                              void* d_out, int out_size) {
    const float* x   = (const float*)d_in[0];
    const float* wq  = (const float*)d_in[1];
    const float* bq  = (const float*)d_in[2];
    const float* wk  = (const float*)d_in[3];
    const float* bk  = (const float*)d_in[4];
    const float* wv  = (const float*)d_in[5];
    const float* bv  = (const float*)d_in[6];
    const float* rh  = (const float*)d_in[7];
    const float* rw  = (const float*)d_in[8];
    const float* rd  = (const float*)d_in[9];
    float* out = (float*)d_out;

    prep_kernel<<<1, 288>>>(rh, rw, rd);

    dim3 tgrid(4, 4, 3);
    wt_kernel<<<tgrid, dim3(32, 8)>>>(wq, wk, wv);

    dim3 ggrid(NV / 128, 3);
    gemm_kernel<<<ggrid, 256>>>(x, bq, bk, bv);

    attn_kernel<<<(S / 2) * (S / 2) * (S / 2), 256>>>(bk, bv, out);
}